// round 10
// baseline (speedup 1.0000x reference)
#include <cuda_runtime.h>
#include <cstdint>
#include <cstddef>

// ============================================================================
// x [4,2048,4096] f32, w [4096,4096] int8-as-int32, out [8192,4096] f32.
// Baseline sm_103 ISA. GEMM via f16 HMMA m16n8k16 (ints in [-127,127] exact in
// f16, f32 accum -> numerics identical to int GEMM).
// A stored in smem as u8 (value+128), expanded to f16 in registers via
// PRMT(0x64|byte) + add.f16x2(-1152)  [1024+u8-1152 = v, exact].
// B stored as f16 in HMMA fragment order.
//   A block (16m x 16k) u8  = 256 B: lane l -> {a0..a3 pairs} at blk*256 + l*8
//   B block ( 8n x 16k) f16 = 256 B: lane l -> {b0,b1}        at blk*256 + l*8
// ============================================================================
#define K_DIM 4096
#define N_DIM 4096
#define M_DIM 8192

#define BM 128
#define BN 128
#define BK 64                   // four 16-k blocks per stage
#define STAGES 4
#define KITERS (K_DIM / BK)     // 64
#define KB16 (K_DIM / 16)       // 256 k-blocks globally

#define A_STAGE_BYTES (8 * 4 * 256)                   // 8192 (u8 A)
#define B_STAGE_BYTES (16 * 4 * 256)                  // 16384 (f16 B)
#define STAGE_BYTES (A_STAGE_BYTES + B_STAGE_BYTES)   // 24576
#define SMEM_TOTAL (STAGES * STAGE_BYTES)             // 98304 (x2 CTAs = 192K <= 228K)

// ============================================================================
// Device scratch
// ============================================================================
__device__ unsigned g_absmax;
__device__ __align__(16) uint8_t  g_xq[(size_t)M_DIM * K_DIM];  // 32 MiB u8 blocked
__device__ __align__(16) uint16_t g_wq[(size_t)N_DIM * K_DIM];  // 32 MiB f16 blocked

// ============================================================================
// PTX helpers
// ============================================================================
__device__ __forceinline__ uint32_t smem_u32(const void* p) {
    uint32_t a;
    asm("{ .reg .u64 t; cvta.to.shared.u64 t, %1; cvt.u32.u64 %0, t; }"
        : "=r"(a) : "l"(p));
    return a;
}

#define CP_ASYNC16(dst, src) \
    asm volatile("cp.async.cg.shared.global [%0], [%1], 16;" :: "r"(dst), "l"(src) : "memory")
#define CP_COMMIT() asm volatile("cp.async.commit_group;" ::: "memory")
#define CP_WAIT(n)  asm volatile("cp.async.wait_group %0;" :: "n"(n) : "memory")

#define LDS64(r0, r1, addr) \
    asm volatile("ld.shared.v2.b32 {%0,%1}, [%2];" \
        : "=r"(r0), "=r"(r1) : "r"(addr))

// u8-pair -> f16x2(1024+u8) via PRMT with 0x64 high bytes, then subtract 1152.
#define MAGIC_HI 0x64646464u
#define MAGIC_SUB 0xE480E480u   // f16x2 (-1152, -1152)
#define PRMT(d, a, sel) \
    asm volatile("prmt.b32 %0, %1, %2, %3;" : "=r"(d) : "r"(a), "n"(MAGIC_HI), "n"(sel))
#define HADD2(d, a, b) \
    asm volatile("add.rn.f16x2 %0, %1, %2;" : "=r"(d) : "r"(a), "r"(b))

// D(f32) = A(16x16 f16) * B(16x8 f16) + D
#define MMA_16816_F16(d, a, b0, b1) \
    asm volatile( \
        "mma.sync.aligned.m16n8k16.row.col.f32.f16.f16.f32 " \
        "{%0,%1,%2,%3}, {%4,%5,%6,%7}, {%8,%9}, {%0,%1,%2,%3};" \
        : "+f"((d)[0]), "+f"((d)[1]), "+f"((d)[2]), "+f"((d)[3]) \
        : "r"((a)[0]), "r"((a)[1]), "r"((a)[2]), "r"((a)[3]), "r"(b0), "r"(b1))

// f16x2 from two exact-int floats (lo in low half)
__device__ __forceinline__ uint32_t pack_f16(float lo, float hi) {
    uint32_t r;
    asm("cvt.rn.f16x2.f32 %0, %1, %2;" : "=r"(r) : "f"(hi), "f"(lo));
    return r;
}

// ============================================================================
// Pass 0: reset absmax
// ============================================================================
__global__ void reset_absmax_kernel() { g_absmax = 0u; }

// ============================================================================
// Pass 1 (fused): absmax of x (blocks [0,1024)) + weight pack to f16 blocked
// layout (blocks [1024, 1024+16384)). The two halves are independent.
// ============================================================================
#define ABSMAX_BLOCKS 1024
#define W_PREP_BLOCKS ((N_DIM / 8) * KB16 * 32 / 256)    // 16384

__global__ void absmax_wprep_kernel(const float4* __restrict__ x, int n4,
                                    const int* __restrict__ w32) {
    if (blockIdx.x < ABSMAX_BLOCKS) {
        float m = 0.0f;
        int stride = ABSMAX_BLOCKS * blockDim.x;
        for (int i = blockIdx.x * blockDim.x + threadIdx.x; i < n4; i += stride) {
            float4 v = x[i];
            m = fmaxf(m, fmaxf(fmaxf(fabsf(v.x), fabsf(v.y)),
                               fmaxf(fabsf(v.z), fabsf(v.w))));
        }
        #pragma unroll
        for (int o = 16; o > 0; o >>= 1)
            m = fmaxf(m, __shfl_xor_sync(0xFFFFFFFFu, m, o));
        __shared__ float wmax[8];
        if ((threadIdx.x & 31) == 0) wmax[threadIdx.x >> 5] = m;
        __syncthreads();
        if (threadIdx.x == 0) {
            float bm = wmax[0];
            #pragma unroll
            for (int i = 1; i < 8; i++) bm = fmaxf(bm, wmax[i]);
            atomicMax(&g_absmax, __float_as_uint(bm));
        }
    } else {
        int id  = (blockIdx.x - ABSMAX_BLOCKS) * 256 + threadIdx.x;
        int l   = id & 31;
        int blk = id >> 5;                   // 0 .. 131071
        int kb  = blk & (KB16 - 1);
        int nb  = blk >> 8;
        int g   = l >> 2;
        int c   = l & 3;
        int n   = nb * 8 + g;
        int k0  = kb * 16 + 2 * c;
        const int* row = w32 + (size_t)n * K_DIM + k0;
        int2 p0 = *reinterpret_cast<const int2*>(row);       // k0, k0+1
        int2 p1 = *reinterpret_cast<const int2*>(row + 8);   // k0+8, k0+9
        uint2 r;
        r.x = pack_f16((float)p0.x, (float)p0.y);            // b0
        r.y = pack_f16((float)p1.x, (float)p1.y);            // b1
        *reinterpret_cast<uint2*>(g_wq + (size_t)blk * 128 + l * 4) = r;
    }
}

// ============================================================================
// Pass 2: quantize x -> g_xq as u8 (value+128) in A-fragment blocked layout.
// Block (16m x 16k) = 256 B. Lane l -> 8 bytes: [a0lo,a0hi,a1lo,a1hi] [a2..a3]
//   a0=(r0, k0..k0+1) a1=(r0+8, ..) a2=(r0, k0+8..) a3=(r0+8, k0+8..)
// ============================================================================
#define X_PREP_BLOCKS ((M_DIM / 16) * KB16 * 32 / 256)   // 16384

__device__ __forceinline__ uint32_t qpack2(float2 va, float2 vb, float s) {
    // bytes: [q(va.x)+128, q(va.y)+128, q(vb.x)+128, q(vb.y)+128]
    int b0 = __float2int_rz(fminf(fmaxf(va.x / s, -127.f), 127.f)) + 128;
    int b1 = __float2int_rz(fminf(fmaxf(va.y / s, -127.f), 127.f)) + 128;
    int b2 = __float2int_rz(fminf(fmaxf(vb.x / s, -127.f), 127.f)) + 128;
    int b3 = __float2int_rz(fminf(fmaxf(vb.y / s, -127.f), 127.f)) + 128;
    return (uint32_t)b0 | ((uint32_t)b1 << 8) | ((uint32_t)b2 << 16) | ((uint32_t)b3 << 24);
}

__global__ void xprep_kernel(const float* __restrict__ x) {
    int id  = blockIdx.x * 256 + threadIdx.x;
    int l   = id & 31;
    int blk = id >> 5;                   // 0 .. 131071
    int kb  = blk & (KB16 - 1);
    int mb  = blk >> 8;                  // 0 .. 511
    int g   = l >> 2;
    int c   = l & 3;
    int r0  = mb * 16 + g;
    int k0  = kb * 16 + 2 * c;
    float s = __uint_as_float(g_absmax) / 127.0f;
    const float* rlo = x + (size_t)r0 * K_DIM + k0;
    const float* rhi = x + (size_t)(r0 + 8) * K_DIM + k0;
    float2 v00 = *reinterpret_cast<const float2*>(rlo);       // a0
    float2 v10 = *reinterpret_cast<const float2*>(rhi);       // a1
    float2 v01 = *reinterpret_cast<const float2*>(rlo + 8);   // a2
    float2 v11 = *reinterpret_cast<const float2*>(rhi + 8);   // a3
    uint2 r;
    r.x = qpack2(v00, v10, s);
    r.y = qpack2(v01, v11, s);
    *reinterpret_cast<uint2*>(g_xq + (size_t)blk * 256 + l * 8) = r;
}

// ============================================================================
// Pass 3: GEMM. CTA 128x128, 512 threads, 16 warps @ 32x32, BK=64, 4 stages.
// A u8 in smem -> f16 via PRMT+HADD2; B f16 in smem.
// ============================================================================
__device__ __forceinline__ void load_stage(uint32_t sA, const uint8_t* gA,
                                           const uint16_t* gB, int kt, int tid) {
    uint32_t sB = sA + A_STAGE_BYTES;
    // A: 32 blocks (8 mb x 4 kb) of 256 B = 512 chunks of 16B, 1 per thread
    {
        int idx = tid;
        int blk = idx >> 4;
        int mb = blk >> 2, kb = blk & 3;
        const uint8_t* src = gA + (size_t)mb * (KB16 * 256)
                               + (size_t)(kt * 4 + kb) * 256 + (idx & 15) * 16;
        CP_ASYNC16(sA + idx * 16, src);
    }
    // B: 64 blocks (16 nb x 4 kb) of 256 B = 1024 chunks of 16B, 2 per thread
    #pragma unroll
    for (int i = 0; i < 2; i++) {
        int idx = tid + i * 512;
        int blk = idx >> 4;
        int nb = blk >> 2, kb = blk & 3;
        const uint16_t* src = gB + (size_t)nb * (KB16 * 128)
                                 + (size_t)(kt * 4 + kb) * 128 + (idx & 15) * 8;
        CP_ASYNC16(sB + idx * 16, src);
    }
}

__global__ __launch_bounds__(512, 2) void gemm_f16_kernel(
    float* __restrict__ out,
    const float* __restrict__ wscale,
    const float* __restrict__ bias)
{
    extern __shared__ char smem[];
    uint32_t sbase = smem_u32(smem);
    int tid  = threadIdx.x;
    int wid  = tid >> 5;
    int lane = tid & 31;
    int m0 = blockIdx.x * BM;
    int n0 = blockIdx.y * BN;

    int warp_m = (wid & 3) * 32;
    int warp_n = (wid >> 2) * 32;

    const uint8_t*  gA = g_xq + (size_t)m0 * K_DIM / 16 * 16;  // = m0*K_DIM bytes-blocked base
    const uint16_t* gB = g_wq + (size_t)n0 * K_DIM;

    int g = lane >> 2;
    int c = lane & 3;

    // Per-lane base addresses within a stage
    uint32_t a_base = (uint32_t)((warp_m >> 4) * 4) * 256 + (uint32_t)lane * 8;
    uint32_t b_base = A_STAGE_BYTES + (uint32_t)((warp_n >> 3) * 4) * 256 + (uint32_t)lane * 8;

    float acc[2][4][4];
    #pragma unroll
    for (int mi = 0; mi < 2; mi++)
        #pragma unroll
        for (int ni = 0; ni < 4; ni++)
            #pragma unroll
            for (int k = 0; k < 4; k++) acc[mi][ni][k] = 0.0f;

    #pragma unroll
    for (int t = 0; t < STAGES - 1; t++) {
        load_stage(sbase + t * STAGE_BYTES, gA, gB, t, tid);
        CP_COMMIT();
    }

    uint32_t msub;
    asm("mov.b32 %0, 0xE480E480;" : "=r"(msub));   // f16x2 (-1152,-1152)

    for (int kt = 0; kt < KITERS; kt++) {
        CP_WAIT(STAGES - 2);
        __syncthreads();

        int t = kt + STAGES - 1;
        if (t < KITERS)
            load_stage(sbase + ((kt + STAGES - 1) % STAGES) * STAGE_BYTES, gA, gB, t, tid);
        CP_COMMIT();

        uint32_t sA = sbase + (kt % STAGES) * STAGE_BYTES;

        #pragma unroll
        for (int ks = 0; ks < 4; ks++) {
            uint32_t a8[2][2];
            #pragma unroll
            for (int mi = 0; mi < 2; mi++)
                LDS64(a8[mi][0], a8[mi][1],
                      sA + a_base + (uint32_t)(((warp_m >> 4) + mi) * 0 + (mi * 4 + ks)) * 256);
            uint32_t bfr[4][2];
            #pragma unroll
            for (int ni = 0; ni < 4; ni++)
                LDS64(bfr[ni][0], bfr[ni][1],
                      sA + b_base + (uint32_t)((ni * 4 + ks) * 256));
            #pragma unroll
            for (int mi = 0; mi < 2; mi++) {
                uint32_t af[4];
                PRMT(af[0], a8[mi][0], 0x4140);   // (a0lo,a0hi) -> f16x2 1024+u8
                PRMT(af[1], a8[mi][0], 0x4342);   // (a1lo,a1hi)
                PRMT(af[2], a8[mi][1], 0x4140);   // (a2lo,a2hi)
                PRMT(af[3], a8[mi][1], 0x4342);   // (a3lo,a3hi)
                HADD2(af[0], af[0], msub);
                HADD2(af[1], af[1], msub);
                HADD2(af[2], af[2], msub);
                HADD2(af[3], af[3], msub);
                #pragma unroll
                for (int ni = 0; ni < 4; ni++)
                    MMA_16816_F16(acc[mi][ni], af, bfr[ni][0], bfr[ni][1]);
            }
        }
    }

    // Epilogue: scale + bias, f32x2 stores
    float combined = (__uint_as_float(g_absmax) / 127.0f) * wscale[0];
    #pragma unroll
    for (int mi = 0; mi < 2; mi++) {
        #pragma unroll
        for (int ni = 0; ni < 4; ni++) {
            int row = m0 + warp_m + mi * 16 + g;
            int col = n0 + warp_n + ni * 8 + c * 2;
            float2 bv = *reinterpret_cast<const float2*>(bias + col);
            float2 v0, v1;
            v0.x = acc[mi][ni][0] * combined + bv.x;
            v0.y = acc[mi][ni][1] * combined + bv.y;
            v1.x = acc[mi][ni][2] * combined + bv.x;
            v1.y = acc[mi][ni][3] * combined + bv.y;
            *reinterpret_cast<float2*>(out + (size_t)row * N_DIM + col) = v0;
            *reinterpret_cast<float2*>(out + (size_t)(row + 8) * N_DIM + col) = v1;
        }
    }
}

// ============================================================================
// kernel_launch
// ============================================================================
extern "C" void kernel_launch(void* const* d_in, const int* in_sizes, int n_in,
                              void* d_out, int out_size) {
    const float* x   = (const float*)d_in[0];
    const int*   w32 = (const int*)d_in[1];
    const float* ws  = (const float*)d_in[2];
    const float* b   = (const float*)d_in[3];
    float* out = (float*)d_out;

    int n4 = in_sizes[0] / 4;

    cudaFuncSetAttribute(gemm_f16_kernel,
                         cudaFuncAttributeMaxDynamicSharedMemorySize, SMEM_TOTAL);

    reset_absmax_kernel<<<1, 1>>>();
    absmax_wprep_kernel<<<ABSMAX_BLOCKS + W_PREP_BLOCKS, 256>>>((const float4*)x, n4, w32);
    xprep_kernel<<<X_PREP_BLOCKS, 256>>>(x);

    dim3 grid(M_DIM / BM, N_DIM / BN);   // 64 x 32
    gemm_f16_kernel<<<grid, 512, SMEM_TOTAL>>>(out, ws, b);
}

// round 11
// speedup vs baseline: 1.0858x; 1.0858x over previous
#include <cuda_runtime.h>
#include <cstdint>
#include <cstddef>

// ============================================================================
// x [4,2048,4096] f32, w [4096,4096] int8-as-int32, out [8192,4096] f32.
// Baseline sm_103 ISA. GEMM via bf16 HMMA m16n8k16 (ints exact in bf16, f32
// accum). Measured engine floor: ~10.2 cyc per mma per SMSP across 3 kernel
// structures -> R9 GEMM retained verbatim. This round trims prepass overhead:
// absmax and weight-pack fused into one launch (independent work).
// Operand layouts (fragment-order blocked):
//   A block (16m x 16k) bf16 = 512 B: lane l -> {a0,a1,a2,a3} at blk*512 + l*16
//   B block ( 8n x 16k) bf16 = 256 B: lane l -> {b0,b1}       at blk*256 + l*8
// ============================================================================
#define K_DIM 4096
#define N_DIM 4096
#define M_DIM 8192

#define BM 128
#define BN 128
#define BK 64                   // four 16-k blocks per stage
#define STAGES 3
#define KITERS (K_DIM / BK)     // 64
#define KB16 (K_DIM / 16)       // 256 k-blocks globally

#define A_STAGE_BYTES (8 * 4 * 512)                   // 16384
#define B_STAGE_BYTES (16 * 4 * 256)                  // 16384
#define STAGE_BYTES (A_STAGE_BYTES + B_STAGE_BYTES)   // 32768
#define SMEM_TOTAL (STAGES * STAGE_BYTES)             // 98304

// ============================================================================
// Device scratch
// ============================================================================
__device__ unsigned g_absmax;
__device__ __align__(16) uint16_t g_xq[(size_t)M_DIM * K_DIM];  // 64 MiB bf16 blocked
__device__ __align__(16) uint16_t g_wq[(size_t)N_DIM * K_DIM];  // 32 MiB bf16 blocked

// ============================================================================
// PTX helpers
// ============================================================================
__device__ __forceinline__ uint32_t smem_u32(const void* p) {
    uint32_t a;
    asm("{ .reg .u64 t; cvta.to.shared.u64 t, %1; cvt.u32.u64 %0, t; }"
        : "=r"(a) : "l"(p));
    return a;
}

#define CP_ASYNC16(dst, src) \
    asm volatile("cp.async.cg.shared.global [%0], [%1], 16;" :: "r"(dst), "l"(src) : "memory")
#define CP_COMMIT() asm volatile("cp.async.commit_group;" ::: "memory")
#define CP_WAIT(n)  asm volatile("cp.async.wait_group %0;" :: "n"(n) : "memory")

#define LDS128(r0, r1, r2, r3, addr) \
    asm volatile("ld.shared.v4.b32 {%0,%1,%2,%3}, [%4];" \
        : "=r"(r0), "=r"(r1), "=r"(r2), "=r"(r3) : "r"(addr))
#define LDS64(r0, r1, addr) \
    asm volatile("ld.shared.v2.b32 {%0,%1}, [%2];" \
        : "=r"(r0), "=r"(r1) : "r"(addr))

// D(f32) = A(16x16 bf16) * B(16x8 bf16) + D
#define MMA_16816_BF16(d, a, b0, b1) \
    asm volatile( \
        "mma.sync.aligned.m16n8k16.row.col.f32.bf16.bf16.f32 " \
        "{%0,%1,%2,%3}, {%4,%5,%6,%7}, {%8,%9}, {%0,%1,%2,%3};" \
        : "+f"((d)[0]), "+f"((d)[1]), "+f"((d)[2]), "+f"((d)[3]) \
        : "r"((a)[0]), "r"((a)[1]), "r"((a)[2]), "r"((a)[3]), "r"(b0), "r"(b1))

__device__ __forceinline__ uint32_t bf16_bits(float f) {
    return __float_as_uint(f) >> 16;   // exact: small-int floats have 0 low mantissa
}
__device__ __forceinline__ uint32_t pack_bf16(float lo, float hi) {
    return bf16_bits(lo) | (bf16_bits(hi) << 16);
}

// ============================================================================
// Pass 0: reset absmax
// ============================================================================
__global__ void reset_absmax_kernel() { g_absmax = 0u; }

// ============================================================================
// Pass 1 (fused): absmax of x (blocks [0,1024)) + weight pack into bf16
// B-fragment blocked layout (blocks [1024, 1024+16384)). Independent halves.
// ============================================================================
#define ABSMAX_BLOCKS 1024
#define W_PREP_BLOCKS ((N_DIM / 8) * KB16 * 32 / 256)    // 16384
#define X_PREP_BLOCKS ((M_DIM / 16) * KB16 * 32 / 256)   // 16384

__global__ void absmax_wprep_kernel(const float4* __restrict__ x, int n4,
                                    const int* __restrict__ w32) {
    if (blockIdx.x < ABSMAX_BLOCKS) {
        float m = 0.0f;
        int stride = ABSMAX_BLOCKS * blockDim.x;
        for (int i = blockIdx.x * blockDim.x + threadIdx.x; i < n4; i += stride) {
            float4 v = x[i];
            m = fmaxf(m, fmaxf(fmaxf(fabsf(v.x), fabsf(v.y)),
                               fmaxf(fabsf(v.z), fabsf(v.w))));
        }
        #pragma unroll
        for (int o = 16; o > 0; o >>= 1)
            m = fmaxf(m, __shfl_xor_sync(0xFFFFFFFFu, m, o));
        __shared__ float wmax[8];
        if ((threadIdx.x & 31) == 0) wmax[threadIdx.x >> 5] = m;
        __syncthreads();
        if (threadIdx.x == 0) {
            float bm = wmax[0];
            #pragma unroll
            for (int i = 1; i < 8; i++) bm = fmaxf(bm, wmax[i]);
            atomicMax(&g_absmax, __float_as_uint(bm));   // vals >= 0: uint order ok
        }
    } else {
        int id  = (blockIdx.x - ABSMAX_BLOCKS) * 256 + threadIdx.x;
        int l   = id & 31;
        int blk = id >> 5;                   // 0 .. 131071
        int kb  = blk & (KB16 - 1);
        int nb  = blk >> 8;
        int g   = l >> 2;
        int c   = l & 3;
        int n   = nb * 8 + g;
        int k0  = kb * 16 + 2 * c;
        const int* row = w32 + (size_t)n * K_DIM + k0;
        int2 p0 = *reinterpret_cast<const int2*>(row);       // k0, k0+1
        int2 p1 = *reinterpret_cast<const int2*>(row + 8);   // k0+8, k0+9
        uint2 r;
        r.x = pack_bf16((float)p0.x, (float)p0.y);           // b0
        r.y = pack_bf16((float)p1.x, (float)p1.y);           // b1
        *reinterpret_cast<uint2*>(g_wq + (size_t)blk * 128 + l * 4) = r;
    }
}

// ============================================================================
// Pass 2: quantize x -> g_xq (bf16, A-fragment blocked layout).
// ============================================================================
__device__ __forceinline__ float q1(float v, float s) {
    return (float)__float2int_rz(fminf(fmaxf(v / s, -127.f), 127.f));
}

__global__ void xprep_kernel(const float* __restrict__ x) {
    int id  = blockIdx.x * 256 + threadIdx.x;
    int l   = id & 31;
    int blk = id >> 5;                   // 0 .. 131071
    int kb  = blk & (KB16 - 1);
    int mb  = blk >> 8;                  // 0 .. 511
    int g   = l >> 2;
    int c   = l & 3;
    int r0  = mb * 16 + g;
    int k0  = kb * 16 + 2 * c;
    float s = __uint_as_float(g_absmax) / 127.0f;
    const float* rlo = x + (size_t)r0 * K_DIM + k0;
    const float* rhi = x + (size_t)(r0 + 8) * K_DIM + k0;
    float2 v00 = *reinterpret_cast<const float2*>(rlo);       // a0
    float2 v10 = *reinterpret_cast<const float2*>(rhi);       // a1
    float2 v01 = *reinterpret_cast<const float2*>(rlo + 8);   // a2
    float2 v11 = *reinterpret_cast<const float2*>(rhi + 8);   // a3
    uint4 r;
    r.x = pack_bf16(q1(v00.x, s), q1(v00.y, s));
    r.y = pack_bf16(q1(v10.x, s), q1(v10.y, s));
    r.z = pack_bf16(q1(v01.x, s), q1(v01.y, s));
    r.w = pack_bf16(q1(v11.x, s), q1(v11.y, s));
    *reinterpret_cast<uint4*>(g_xq + (size_t)blk * 256 + l * 8) = r;
}

// ============================================================================
// Pass 3: bf16 GEMM (R9 verbatim — measured best). CTA 128x128, 512 threads,
// 16 warps @ 32x32, BK=64, 3-stage cp.async pipeline.
// ============================================================================
__device__ __forceinline__ void load_stage(uint32_t sA, const uint16_t* gA,
                                           const uint16_t* gB, int kt, int tid) {
    uint32_t sB = sA + A_STAGE_BYTES;
    #pragma unroll
    for (int i = 0; i < 2; i++) {
        int idx = tid + i * 512;
        int blk = idx >> 5;
        int mb = blk >> 2, kb = blk & 3;
        const uint16_t* src = gA + (size_t)mb * (KB16 * 256)
                                 + (size_t)(kt * 4 + kb) * 256 + (idx & 31) * 8;
        CP_ASYNC16(sA + idx * 16, src);
    }
    #pragma unroll
    for (int i = 0; i < 2; i++) {
        int idx = tid + i * 512;
        int blk = idx >> 4;
        int nb = blk >> 2, kb = blk & 3;
        const uint16_t* src = gB + (size_t)nb * (KB16 * 128)
                                 + (size_t)(kt * 4 + kb) * 128 + (idx & 15) * 8;
        CP_ASYNC16(sB + idx * 16, src);
    }
}

__global__ __launch_bounds__(512, 2) void gemm_bf16_kernel(
    float* __restrict__ out,
    const float* __restrict__ wscale,
    const float* __restrict__ bias)
{
    extern __shared__ char smem[];
    uint32_t sbase = smem_u32(smem);
    int tid  = threadIdx.x;
    int wid  = tid >> 5;
    int lane = tid & 31;
    int m0 = blockIdx.x * BM;
    int n0 = blockIdx.y * BN;

    int warp_m = (wid & 3) * 32;
    int warp_n = (wid >> 2) * 32;

    const uint16_t* gA = g_xq + (size_t)m0 * K_DIM;
    const uint16_t* gB = g_wq + (size_t)n0 * K_DIM;

    int g = lane >> 2;
    int c = lane & 3;

    uint32_t a_base = (uint32_t)((warp_m >> 4) * 4) * 512 + (uint32_t)lane * 16;
    uint32_t b_base = A_STAGE_BYTES + (uint32_t)((warp_n >> 3) * 4) * 256 + (uint32_t)lane * 8;

    float acc[2][4][4];
    #pragma unroll
    for (int mi = 0; mi < 2; mi++)
        #pragma unroll
        for (int ni = 0; ni < 4; ni++)
            #pragma unroll
            for (int k = 0; k < 4; k++) acc[mi][ni][k] = 0.0f;

    #pragma unroll
    for (int t = 0; t < STAGES - 1; t++) {
        load_stage(sbase + t * STAGE_BYTES, gA, gB, t, tid);
        CP_COMMIT();
    }

    for (int kt = 0; kt < KITERS; kt++) {
        CP_WAIT(STAGES - 2);
        __syncthreads();

        int t = kt + STAGES - 1;
        if (t < KITERS)
            load_stage(sbase + ((kt + STAGES - 1) % STAGES) * STAGE_BYTES, gA, gB, t, tid);
        CP_COMMIT();

        uint32_t sA = sbase + (kt % STAGES) * STAGE_BYTES;

        #pragma unroll
        for (int ks = 0; ks < 4; ks++) {
            uint32_t afr[2][4];
            #pragma unroll
            for (int mi = 0; mi < 2; mi++)
                LDS128(afr[mi][0], afr[mi][1], afr[mi][2], afr[mi][3],
                       sA + a_base + (uint32_t)((mi * 4 + ks) * 512));
            uint32_t bfr[4][2];
            #pragma unroll
            for (int ni = 0; ni < 4; ni++)
                LDS64(bfr[ni][0], bfr[ni][1],
                      sA + b_base + (uint32_t)((ni * 4 + ks) * 256));
            #pragma unroll
            for (int mi = 0; mi < 2; mi++)
                #pragma unroll
                for (int ni = 0; ni < 4; ni++)
                    MMA_16816_BF16(acc[mi][ni], afr[mi], bfr[ni][0], bfr[ni][1]);
        }
    }

    // Epilogue: scale + bias, f32x2 stores
    float combined = (__uint_as_float(g_absmax) / 127.0f) * wscale[0];
    #pragma unroll
    for (int mi = 0; mi < 2; mi++) {
        #pragma unroll
        for (int ni = 0; ni < 4; ni++) {
            int row = m0 + warp_m + mi * 16 + g;
            int col = n0 + warp_n + ni * 8 + c * 2;
            float2 bv = *reinterpret_cast<const float2*>(bias + col);
            float2 v0, v1;
            v0.x = acc[mi][ni][0] * combined + bv.x;
            v0.y = acc[mi][ni][1] * combined + bv.y;
            v1.x = acc[mi][ni][2] * combined + bv.x;
            v1.y = acc[mi][ni][3] * combined + bv.y;
            *reinterpret_cast<float2*>(out + (size_t)row * N_DIM + col) = v0;
            *reinterpret_cast<float2*>(out + (size_t)(row + 8) * N_DIM + col) = v1;
        }
    }
}

// ============================================================================
// kernel_launch
// ============================================================================
extern "C" void kernel_launch(void* const* d_in, const int* in_sizes, int n_in,
                              void* d_out, int out_size) {
    const float* x   = (const float*)d_in[0];
    const int*   w32 = (const int*)d_in[1];
    const float* ws  = (const float*)d_in[2];
    const float* b   = (const float*)d_in[3];
    float* out = (float*)d_out;

    int n4 = in_sizes[0] / 4;

    cudaFuncSetAttribute(gemm_bf16_kernel,
                         cudaFuncAttributeMaxDynamicSharedMemorySize, SMEM_TOTAL);

    reset_absmax_kernel<<<1, 1>>>();
    absmax_wprep_kernel<<<ABSMAX_BLOCKS + W_PREP_BLOCKS, 256>>>((const float4*)x, n4, w32);
    xprep_kernel<<<X_PREP_BLOCKS, 256>>>(x);

    dim3 grid(M_DIM / BM, N_DIM / BN);   // 64 x 32
    gemm_bf16_kernel<<<grid, 512, SMEM_TOTAL>>>(out, ws, b);
}